// round 3
// baseline (speedup 1.0000x reference)
#include <cuda_runtime.h>
#include <cstdint>
#include <math.h>

#define H_IN    24
#define F       50
#define FP      52      // padded feature stride (52*4=208 bytes, 16B aligned)
#define DH      100
#define DT      0.0625f
#define SQDT    0.25f
#define SIG     5.0f

// ---------------- Threefry-2x32 (matches JAX) ----------------
__device__ __forceinline__ void tf_round(uint32_t& x0, uint32_t& x1, int r) {
    x0 += x1;
    x1 = __funnelshift_l(x1, x1, r);
    x1 ^= x0;
}

// Full threefry (used for fold_in key derivation)
__device__ __forceinline__ void threefry2x32(uint32_t k0, uint32_t k1,
                                             uint32_t c0, uint32_t c1,
                                             uint32_t& o0, uint32_t& o1) {
    uint32_t k2 = k0 ^ k1 ^ 0x1BD11BDAu;
    uint32_t x0 = c0 + k0, x1 = c1 + k1;
    tf_round(x0,x1,13); tf_round(x0,x1,15); tf_round(x0,x1,26); tf_round(x0,x1, 6);
    x0 += k1; x1 += k2 + 1u;
    tf_round(x0,x1,17); tf_round(x0,x1,29); tf_round(x0,x1,16); tf_round(x0,x1,24);
    x0 += k2; x1 += k0 + 2u;
    tf_round(x0,x1,13); tf_round(x0,x1,15); tf_round(x0,x1,26); tf_round(x0,x1, 6);
    x0 += k0; x1 += k1 + 3u;
    tf_round(x0,x1,17); tf_round(x0,x1,29); tf_round(x0,x1,16); tf_round(x0,x1,24);
    x0 += k1; x1 += k2 + 4u;
    tf_round(x0,x1,13); tf_round(x0,x1,15); tf_round(x0,x1,26); tf_round(x0,x1, 6);
    o0 = x0 + k2;
    o1 = x1 + k0 + 5u;
}

// Partitionable-mode random bits for sample index j (< 2^32):
// counter = (0, j); bits = out0 ^ out1. c0 = 0 is folded in (x0 starts at k0).
__device__ __forceinline__ uint32_t tf_bits_c0zero(uint32_t k0, uint32_t k1,
                                                   uint32_t k2, uint32_t c1) {
    uint32_t x0 = k0;
    uint32_t x1 = c1 + k1;
    tf_round(x0,x1,13); tf_round(x0,x1,15); tf_round(x0,x1,26); tf_round(x0,x1, 6);
    x0 += k1; x1 += k2 + 1u;
    tf_round(x0,x1,17); tf_round(x0,x1,29); tf_round(x0,x1,16); tf_round(x0,x1,24);
    x0 += k2; x1 += k0 + 2u;
    tf_round(x0,x1,13); tf_round(x0,x1,15); tf_round(x0,x1,26); tf_round(x0,x1, 6);
    x0 += k0; x1 += k1 + 3u;
    tf_round(x0,x1,17); tf_round(x0,x1,29); tf_round(x0,x1,16); tf_round(x0,x1,24);
    x0 += k1; x1 += k2 + 4u;
    tf_round(x0,x1,13); tf_round(x0,x1,15); tf_round(x0,x1,26); tf_round(x0,x1, 6);
    return (x0 + k2) ^ (x1 + k0 + 5u);
}

// XLA ErfInv f32 (Giles polynomial, exactly as xla/client/lib/math.cc)
__device__ __forceinline__ float xla_erfinv(float x) {
    float xx = x * x;
    float w = -log1pf(-xx);
    float p;
    if (w < 5.0f) {
        w = w - 2.5f;
        p = 2.81022636e-08f;
        p = fmaf(p, w, 3.43273939e-07f);
        p = fmaf(p, w, -3.5233877e-06f);
        p = fmaf(p, w, -4.39150654e-06f);
        p = fmaf(p, w, 0.00021858087f);
        p = fmaf(p, w, -0.00125372503f);
        p = fmaf(p, w, -0.00417768164f);
        p = fmaf(p, w, 0.246640727f);
        p = fmaf(p, w, 1.50140941f);
    } else {
        w = sqrtf(w) - 3.0f;
        p = -0.000200214257f;
        p = fmaf(p, w, 0.000100950558f);
        p = fmaf(p, w, 0.00134934322f);
        p = fmaf(p, w, -0.00367342844f);
        p = fmaf(p, w, 0.00573950773f);
        p = fmaf(p, w, -0.0076224613f);
        p = fmaf(p, w, 0.00943887047f);
        p = fmaf(p, w, 1.00167406f);
        p = fmaf(p, w, 2.83297682f);
    }
    return p * x;
}

// bits -> N(0,1) sample, matching jax.random.normal (threefry, partitionable)
__device__ __forceinline__ float bits_to_normal(uint32_t bits) {
    float r = __uint_as_float(0x3f800000u | (bits >> 9)) - 1.0f;   // [0,1)
    float u = fmaf(r, 2.0f, -0.99999994f);                          // hi-lo rounds to 2.0f
    u = fmaxf(u, -0.99999994f);
    return 1.41421356f * xla_erfinv(u);
}

__global__ void __launch_bounds__(128, 3)
sde_kernel(const float* __restrict__ x,
           const float* __restrict__ W_down,  const float* __restrict__ b_down,
           const float* __restrict__ W_drift, const float* __restrict__ b_drift,
           const float* __restrict__ W_diff1, const float* __restrict__ b_diff1,
           const float* __restrict__ W_diff2, const float* __restrict__ b_diff2,
           const float* __restrict__ W_fc,    const float* __restrict__ b_fc,
           float* __restrict__ out, int N)
{
    __shared__ float sWdown[H_IN * FP];
    __shared__ float sWd[F * FP];
    __shared__ float sW1T[DH * FP];     // transposed diff1: [m][j]
    __shared__ float sW2[DH];
    __shared__ float sB1[DH];
    __shared__ float sBdown[FP];
    __shared__ float sBdrift[FP];
    __shared__ float sWfc[2 * F];       // [k*2+c]
    __shared__ uint32_t sK0[64], sK1[64];

    const int tid = threadIdx.x;

    for (int idx = tid; idx < H_IN * FP; idx += blockDim.x) {
        int h = idx / FP, k = idx - h * FP;
        sWdown[idx] = (k < F) ? W_down[h * F + k] : 0.0f;
    }
    for (int idx = tid; idx < F * FP; idx += blockDim.x) {
        int j = idx / FP, k = idx - j * FP;
        sWd[idx] = (k < F) ? W_drift[j * F + k] : 0.0f;
    }
    for (int idx = tid; idx < DH * FP; idx += blockDim.x) {
        int m = idx / FP, j = idx - m * FP;
        sW1T[idx] = (j < F) ? W_diff1[j * DH + m] : 0.0f;
    }
    for (int idx = tid; idx < DH; idx += blockDim.x) {
        sW2[idx] = W_diff2[idx];
        sB1[idx] = b_diff1[idx];
        sWfc[idx] = W_fc[idx];
    }
    for (int idx = tid; idx < FP; idx += blockDim.x) {
        sBdown[idx]  = (idx < F) ? b_down[idx]  : 0.0f;
        sBdrift[idx] = (idx < F) ? b_drift[idx] : 0.0f;
    }
    // per-step fold_in keys: threefry((0,42), (0,i))
    if (tid < 64) {
        uint32_t a, b;
        threefry2x32(0u, 42u, 0u, (uint32_t)tid, a, b);
        sK0[tid] = a; sK1[tid] = b;
    }
    __syncthreads();

    const uint32_t t = blockIdx.x * blockDim.x + tid;   // one token per thread
    if (t >= (uint32_t)N) return;
    const uint32_t cbase = t * 50u;                     // flattened sample base

    // ---- downsample: o = x @ W_down + b_down ----
    // o padded to FP so float4 reads at q=12 are in-bounds and exactly zero.
    float o[FP];
    o[50] = 0.0f; o[51] = 0.0f;
    float coef;
    {
        float acc[FP];
        {
            const float4* bb = reinterpret_cast<const float4*>(sBdown);
            #pragma unroll
            for (int q = 0; q < 13; q++) {
                float4 b4 = bb[q];
                acc[4*q] = b4.x; acc[4*q+1] = b4.y; acc[4*q+2] = b4.z; acc[4*q+3] = b4.w;
            }
        }
        const float* xp = x + (size_t)t * H_IN;
        #pragma unroll
        for (int h = 0; h < H_IN; h++) {
            float xv = __ldg(xp + h);
            const float4* wrow = reinterpret_cast<const float4*>(&sWdown[h * FP]);
            #pragma unroll
            for (int q = 0; q < 13; q++) {
                float4 w = wrow[q];
                acc[4*q]   = fmaf(xv, w.x, acc[4*q]);
                acc[4*q+1] = fmaf(xv, w.y, acc[4*q+1]);
                acc[4*q+2] = fmaf(xv, w.z, acc[4*q+2]);
                acc[4*q+3] = fmaf(xv, w.w, acc[4*q+3]);
            }
        }
        #pragma unroll
        for (int k = 0; k < F; k++) o[k] = acc[k];

        // ---- diffusion net at t=0: coef = SIGMA * sigmoid(relu(o@W1+b1)@W2 + b2) * sqrt(dt)
        float ds = __ldg(b_diff2);
        #pragma unroll 4
        for (int m = 0; m < DH; m++) {
            float s = sB1[m];
            const float4* wrow = reinterpret_cast<const float4*>(&sW1T[m * FP]);
            #pragma unroll
            for (int q = 0; q < 13; q++) {
                float4 w = wrow[q];
                s = fmaf(o[4*q],   w.x, s);
                s = fmaf(o[4*q+1], w.y, s);
                s = fmaf(o[4*q+2], w.z, s);
                s = fmaf(o[4*q+3], w.w, s);
            }
            ds = fmaf(fmaxf(s, 0.0f), sW2[m], ds);
        }
        coef = SIG * (1.0f / (1.0f + expf(-ds))) * SQDT;
    }

    // ---- 64 SDE steps ----
    for (int i = 0; i < 64; i++) {
        const uint32_t fk0 = sK0[i], fk1 = sK1[i];
        const uint32_t fk2 = fk0 ^ fk1 ^ 0x1BD11BDAu;

        // drift pre-activation: acc = o @ W_drift + b_drift
        float acc[FP];
        {
            const float4* bb = reinterpret_cast<const float4*>(sBdrift);
            #pragma unroll
            for (int q = 0; q < 13; q++) {
                float4 b4 = bb[q];
                acc[4*q] = b4.x; acc[4*q+1] = b4.y; acc[4*q+2] = b4.z; acc[4*q+3] = b4.w;
            }
        }
        #pragma unroll
        for (int j = 0; j < F; j++) {
            float oj = o[j];
            const float4* wrow = reinterpret_cast<const float4*>(&sWd[j * FP]);
            #pragma unroll
            for (int q = 0; q < 13; q++) {
                float4 w = wrow[q];
                acc[4*q]   = fmaf(oj, w.x, acc[4*q]);
                acc[4*q+1] = fmaf(oj, w.y, acc[4*q+1]);
                acc[4*q+2] = fmaf(oj, w.z, acc[4*q+2]);
                acc[4*q+3] = fmaf(oj, w.w, acc[4*q+3]);
            }
        }

        // noise + update: partitionable threefry, one full call per sample,
        // bits = out0 ^ out1 at counter (0, cbase + f)
        #pragma unroll
        for (int f = 0; f < F; f++) {
            uint32_t bits = tf_bits_c0zero(fk0, fk1, fk2, cbase + (uint32_t)f);
            float z = bits_to_normal(bits);
            o[f] = fmaf(coef, z, fmaf(fmaxf(acc[f], 0.0f), DT, o[f]));
        }
    }

    // ---- head: final = relu(o) @ W_fc + b_fc; mu, softplus(sigma)+1e-3 ----
    float mu = __ldg(b_fc + 0);
    float sg = __ldg(b_fc + 1);
    #pragma unroll
    for (int k = 0; k < F; k++) {
        float r = fmaxf(o[k], 0.0f);
        mu = fmaf(r, sWfc[2*k],     mu);
        sg = fmaf(r, sWfc[2*k + 1], sg);
    }
    float sigma = fmaxf(sg, 0.0f) + log1pf(expf(-fabsf(sg))) + 0.001f;

    out[t] = mu;
    out[(size_t)N + t] = sigma;
}

extern "C" void kernel_launch(void* const* d_in, const int* in_sizes, int n_in,
                              void* d_out, int out_size)
{
    const float* x       = (const float*)d_in[0];
    const float* W_down  = (const float*)d_in[1];
    const float* b_down  = (const float*)d_in[2];
    const float* W_drift = (const float*)d_in[3];
    const float* b_drift = (const float*)d_in[4];
    const float* W_diff1 = (const float*)d_in[5];
    const float* b_diff1 = (const float*)d_in[6];
    const float* W_diff2 = (const float*)d_in[7];
    const float* b_diff2 = (const float*)d_in[8];
    const float* W_fc    = (const float*)d_in[9];
    const float* b_fc    = (const float*)d_in[10];

    int N = in_sizes[0] / H_IN;          // number of tokens (B*L)
    int threads = 128;
    int blocks = (N + threads - 1) / threads;

    sde_kernel<<<blocks, threads>>>(x, W_down, b_down, W_drift, b_drift,
                                    W_diff1, b_diff1, W_diff2, b_diff2,
                                    W_fc, b_fc, (float*)d_out, N);
}

// round 4
// speedup vs baseline: 1.7122x; 1.7122x over previous
#include <cuda_runtime.h>
#include <cstdint>
#include <math.h>

#define H_IN    24
#define F       50
#define FP      52      // padded feature stride (52*4=208 bytes, 16B aligned)
#define DH      100
#define DT      0.0625f
#define SQDT    0.25f
#define SIG     5.0f

// ---------------- packed f32x2 helpers (Blackwell FFMA2 path) ----------------
__device__ __forceinline__ uint64_t pack2(float lo, float hi) {
    uint64_t r;
    asm("mov.b64 %0, {%1, %2};" : "=l"(r) : "f"(lo), "f"(hi));
    return r;
}
__device__ __forceinline__ float2 unpack2(uint64_t v) {
    float2 r;
    asm("mov.b64 {%0, %1}, %2;" : "=f"(r.x), "=f"(r.y) : "l"(v));
    return r;
}
__device__ __forceinline__ void ffma2(uint64_t& d, uint64_t a, uint64_t b) {
    asm("fma.rn.f32x2 %0, %1, %2, %0;" : "+l"(d) : "l"(a), "l"(b));
}

// ---------------- Threefry-2x32 (matches JAX) ----------------
__device__ __forceinline__ void tf_round(uint32_t& x0, uint32_t& x1, int r) {
    x0 += x1;
    x1 = __funnelshift_l(x1, x1, r);
    x1 ^= x0;
}

// Full threefry (used for fold_in key derivation)
__device__ __forceinline__ void threefry2x32(uint32_t k0, uint32_t k1,
                                             uint32_t c0, uint32_t c1,
                                             uint32_t& o0, uint32_t& o1) {
    uint32_t k2 = k0 ^ k1 ^ 0x1BD11BDAu;
    uint32_t x0 = c0 + k0, x1 = c1 + k1;
    tf_round(x0,x1,13); tf_round(x0,x1,15); tf_round(x0,x1,26); tf_round(x0,x1, 6);
    x0 += k1; x1 += k2 + 1u;
    tf_round(x0,x1,17); tf_round(x0,x1,29); tf_round(x0,x1,16); tf_round(x0,x1,24);
    x0 += k2; x1 += k0 + 2u;
    tf_round(x0,x1,13); tf_round(x0,x1,15); tf_round(x0,x1,26); tf_round(x0,x1, 6);
    x0 += k0; x1 += k1 + 3u;
    tf_round(x0,x1,17); tf_round(x0,x1,29); tf_round(x0,x1,16); tf_round(x0,x1,24);
    x0 += k1; x1 += k2 + 4u;
    tf_round(x0,x1,13); tf_round(x0,x1,15); tf_round(x0,x1,26); tf_round(x0,x1, 6);
    o0 = x0 + k2;
    o1 = x1 + k0 + 5u;
}

// Partitionable-mode random bits for sample index j (< 2^32):
// counter = (0, j); bits = out0 ^ out1. c0 = 0 is folded in (x0 starts at k0).
__device__ __forceinline__ uint32_t tf_bits_c0zero(uint32_t k0, uint32_t k1,
                                                   uint32_t k2, uint32_t c1) {
    uint32_t x0 = k0;
    uint32_t x1 = c1 + k1;
    tf_round(x0,x1,13); tf_round(x0,x1,15); tf_round(x0,x1,26); tf_round(x0,x1, 6);
    x0 += k1; x1 += k2 + 1u;
    tf_round(x0,x1,17); tf_round(x0,x1,29); tf_round(x0,x1,16); tf_round(x0,x1,24);
    x0 += k2; x1 += k0 + 2u;
    tf_round(x0,x1,13); tf_round(x0,x1,15); tf_round(x0,x1,26); tf_round(x0,x1, 6);
    x0 += k0; x1 += k1 + 3u;
    tf_round(x0,x1,17); tf_round(x0,x1,29); tf_round(x0,x1,16); tf_round(x0,x1,24);
    x0 += k1; x1 += k2 + 4u;
    tf_round(x0,x1,13); tf_round(x0,x1,15); tf_round(x0,x1,26); tf_round(x0,x1, 6);
    return (x0 + k2) ^ (x1 + k0 + 5u);
}

// XLA ErfInv f32 (Giles polynomial), with cheap factored log:
// w = -log(1-x^2) = -log((1-x)(1+x)); 1±x are (near-)exact by Sterbenz.
__device__ __forceinline__ float xla_erfinv_fast(float x) {
    float w = -__logf((1.0f - x) * (1.0f + x));
    float p;
    if (w < 5.0f) {
        w = w - 2.5f;
        p = 2.81022636e-08f;
        p = fmaf(p, w, 3.43273939e-07f);
        p = fmaf(p, w, -3.5233877e-06f);
        p = fmaf(p, w, -4.39150654e-06f);
        p = fmaf(p, w, 0.00021858087f);
        p = fmaf(p, w, -0.00125372503f);
        p = fmaf(p, w, -0.00417768164f);
        p = fmaf(p, w, 0.246640727f);
        p = fmaf(p, w, 1.50140941f);
    } else {
        w = sqrtf(w) - 3.0f;
        p = -0.000200214257f;
        p = fmaf(p, w, 0.000100950558f);
        p = fmaf(p, w, 0.00134934322f);
        p = fmaf(p, w, -0.00367342844f);
        p = fmaf(p, w, 0.00573950773f);
        p = fmaf(p, w, -0.0076224613f);
        p = fmaf(p, w, 0.00943887047f);
        p = fmaf(p, w, 1.00167406f);
        p = fmaf(p, w, 2.83297682f);
    }
    return p * x;
}

// bits -> N(0,1) sample, matching jax.random.normal (threefry, partitionable)
__device__ __forceinline__ float bits_to_normal(uint32_t bits) {
    float r = __uint_as_float(0x3f800000u | (bits >> 9)) - 1.0f;   // [0,1)
    float u = fmaf(r, 2.0f, -0.99999994f);                          // hi-lo rounds to 2.0f
    u = fmaxf(u, -0.99999994f);
    return 1.41421356f * xla_erfinv_fast(u);
}

__global__ void __launch_bounds__(128, 3)
sde_kernel(const float* __restrict__ x,
           const float* __restrict__ W_down,  const float* __restrict__ b_down,
           const float* __restrict__ W_drift, const float* __restrict__ b_drift,
           const float* __restrict__ W_diff1, const float* __restrict__ b_diff1,
           const float* __restrict__ W_diff2, const float* __restrict__ b_diff2,
           const float* __restrict__ W_fc,    const float* __restrict__ b_fc,
           float* __restrict__ out, int N)
{
    __shared__ float sWdown[H_IN * FP];
    __shared__ float sWd[F * FP];
    __shared__ float sW1T[DH * FP];     // transposed diff1: [m][j]
    __shared__ float sW2[DH];
    __shared__ float sB1[DH];
    __shared__ float sBdown[FP];
    __shared__ float sBdrift[FP];
    __shared__ float sWfc[2 * F];       // [k*2+c]
    __shared__ uint32_t sK0[64], sK1[64];

    const int tid = threadIdx.x;

    for (int idx = tid; idx < H_IN * FP; idx += blockDim.x) {
        int h = idx / FP, k = idx - h * FP;
        sWdown[idx] = (k < F) ? W_down[h * F + k] : 0.0f;
    }
    for (int idx = tid; idx < F * FP; idx += blockDim.x) {
        int j = idx / FP, k = idx - j * FP;
        sWd[idx] = (k < F) ? W_drift[j * F + k] : 0.0f;
    }
    for (int idx = tid; idx < DH * FP; idx += blockDim.x) {
        int m = idx / FP, j = idx - m * FP;
        sW1T[idx] = (j < F) ? W_diff1[j * DH + m] : 0.0f;
    }
    for (int idx = tid; idx < DH; idx += blockDim.x) {
        sW2[idx] = W_diff2[idx];
        sB1[idx] = b_diff1[idx];
        sWfc[idx] = W_fc[idx];
    }
    for (int idx = tid; idx < FP; idx += blockDim.x) {
        sBdown[idx]  = (idx < F) ? b_down[idx]  : 0.0f;
        sBdrift[idx] = (idx < F) ? b_drift[idx] : 0.0f;
    }
    // per-step fold_in keys: threefry((0,42), (0,i))
    if (tid < 64) {
        uint32_t a, b;
        threefry2x32(0u, 42u, 0u, (uint32_t)tid, a, b);
        sK0[tid] = a; sK1[tid] = b;
    }
    __syncthreads();

    const uint32_t t = blockIdx.x * blockDim.x + tid;   // one token per thread
    if (t >= (uint32_t)N) return;
    const uint32_t cbase = t * 50u;                     // flattened sample base

    // ---- downsample: o = x @ W_down + b_down (packed f32x2) ----
    float o[FP];
    o[50] = 0.0f; o[51] = 0.0f;
    float coef;
    {
        uint64_t accp[26];
        {
            const ulonglong2* bb = reinterpret_cast<const ulonglong2*>(sBdown);
            #pragma unroll
            for (int q = 0; q < 13; q++) {
                ulonglong2 b2 = bb[q];
                accp[2*q] = b2.x; accp[2*q+1] = b2.y;
            }
        }
        const float* xp = x + (size_t)t * H_IN;
        #pragma unroll
        for (int h = 0; h < H_IN; h++) {
            float xv = __ldg(xp + h);
            uint64_t xvv = pack2(xv, xv);
            const ulonglong2* wrow = reinterpret_cast<const ulonglong2*>(&sWdown[h * FP]);
            #pragma unroll
            for (int q = 0; q < 13; q++) {
                ulonglong2 w = wrow[q];
                ffma2(accp[2*q],   xvv, w.x);
                ffma2(accp[2*q+1], xvv, w.y);
            }
        }
        #pragma unroll
        for (int q = 0; q < 25; q++) {
            float2 v = unpack2(accp[q]);
            o[2*q] = v.x; o[2*q+1] = v.y;
        }

        // ---- diffusion net at t=0: coef = SIGMA*sigmoid(relu(o@W1+b1)@W2+b2)*sqrt(dt)
        uint64_t op[26];
        #pragma unroll
        for (int q = 0; q < 26; q++) op[q] = pack2(o[2*q], o[2*q+1]);

        float ds = __ldg(b_diff2);
        #pragma unroll 4
        for (int m = 0; m < DH; m++) {
            uint64_t sp = pack2(sB1[m], 0.0f);
            const ulonglong2* wrow = reinterpret_cast<const ulonglong2*>(&sW1T[m * FP]);
            #pragma unroll
            for (int q = 0; q < 13; q++) {
                ulonglong2 w = wrow[q];
                ffma2(sp, op[2*q],   w.x);
                ffma2(sp, op[2*q+1], w.y);
            }
            float2 sv = unpack2(sp);
            float s = sv.x + sv.y;
            ds = fmaf(fmaxf(s, 0.0f), sW2[m], ds);
        }
        coef = SIG * (1.0f / (1.0f + expf(-ds))) * SQDT;
    }

    // ---- 64 SDE steps ----
    for (int i = 0; i < 64; i++) {
        const uint32_t fk0 = sK0[i], fk1 = sK1[i];
        const uint32_t fk2 = fk0 ^ fk1 ^ 0x1BD11BDAu;

        // drift pre-activation (packed): accp = o @ W_drift + b_drift
        uint64_t accp[26];
        {
            const ulonglong2* bb = reinterpret_cast<const ulonglong2*>(sBdrift);
            #pragma unroll
            for (int q = 0; q < 13; q++) {
                ulonglong2 b2 = bb[q];
                accp[2*q] = b2.x; accp[2*q+1] = b2.y;
            }
        }
        #pragma unroll 10
        for (int j = 0; j < F; j++) {
            float oj = o[j];
            uint64_t ojj = pack2(oj, oj);
            const ulonglong2* wrow = reinterpret_cast<const ulonglong2*>(&sWd[j * FP]);
            #pragma unroll
            for (int q = 0; q < 13; q++) {
                ulonglong2 w = wrow[q];
                ffma2(accp[2*q],   ojj, w.x);
                ffma2(accp[2*q+1], ojj, w.y);
            }
        }

        // unpack drift pre-activation to scalars
        float acc[FP];
        #pragma unroll
        for (int q = 0; q < 25; q++) {
            float2 v = unpack2(accp[q]);
            acc[2*q] = v.x; acc[2*q+1] = v.y;
        }

        // noise + update: partitionable threefry, bits = out0^out1 at (0, cbase+f)
        #pragma unroll 10
        for (int f = 0; f < F; f++) {
            uint32_t bits = tf_bits_c0zero(fk0, fk1, fk2, cbase + (uint32_t)f);
            float z = bits_to_normal(bits);
            o[f] = fmaf(coef, z, fmaf(fmaxf(acc[f], 0.0f), DT, o[f]));
        }
    }

    // ---- head: final = relu(o) @ W_fc + b_fc; mu, softplus(sigma)+1e-3 ----
    float mu = __ldg(b_fc + 0);
    float sg = __ldg(b_fc + 1);
    #pragma unroll
    for (int k = 0; k < F; k++) {
        float r = fmaxf(o[k], 0.0f);
        mu = fmaf(r, sWfc[2*k],     mu);
        sg = fmaf(r, sWfc[2*k + 1], sg);
    }
    float sigma = fmaxf(sg, 0.0f) + log1pf(expf(-fabsf(sg))) + 0.001f;

    out[t] = mu;
    out[(size_t)N + t] = sigma;
}

extern "C" void kernel_launch(void* const* d_in, const int* in_sizes, int n_in,
                              void* d_out, int out_size)
{
    const float* x       = (const float*)d_in[0];
    const float* W_down  = (const float*)d_in[1];
    const float* b_down  = (const float*)d_in[2];
    const float* W_drift = (const float*)d_in[3];
    const float* b_drift = (const float*)d_in[4];
    const float* W_diff1 = (const float*)d_in[5];
    const float* b_diff1 = (const float*)d_in[6];
    const float* W_diff2 = (const float*)d_in[7];
    const float* b_diff2 = (const float*)d_in[8];
    const float* W_fc    = (const float*)d_in[9];
    const float* b_fc    = (const float*)d_in[10];

    int N = in_sizes[0] / H_IN;          // number of tokens (B*L)
    int threads = 128;
    int blocks = (N + threads - 1) / threads;

    sde_kernel<<<blocks, threads>>>(x, W_down, b_down, W_drift, b_drift,
                                    W_diff1, b_diff1, W_diff2, b_diff2,
                                    W_fc, b_fc, (float*)d_out, N);
}